// round 3
// baseline (speedup 1.0000x reference)
#include <cuda_runtime.h>
#include <math.h>

constexpr int S = 4;
constexpr int V = 2;
constexpr int B = 8192;
constexpr int D = 512;
constexpr int KV = S * V;            // 8 vectors per batch element
constexpr float TEMP_INV = 10.0f;    // 1 / 0.1

constexpr int WARPS_PER_BLOCK = 8;
constexpr int THREADS = WARPS_PER_BLOCK * 32;
constexpr int NBLOCKS = B / WARPS_PER_BLOCK;  // 1024

// Only pairs the loss actually uses: diagonals (norms), even-odd (pos +
// anchor-vs-v1 negatives), even-even off-diag (anchor-vs-v0 negatives).
// Odd-odd off-diagonal pairs are never read -> skip them. 30 pairs total.
__host__ __device__ constexpr bool pair_skip(int p, int q) {
    return (p & 1) && (q & 1) && (p != q);
}
__host__ __device__ constexpr int pidx(int p, int q) {
    int idx = 0;
    for (int a = 0; a < KV; a++)
        for (int b = a; b < KV; b++) {
            if (pair_skip(a, b)) continue;
            if (a == p && b == q) return idx;
            idx++;
        }
    return -1;
}
constexpr int NPAIR = pidx(KV - 1, KV - 1) + 1;  // 30

// Deterministic fused reduction scratch (allocation-free)
__device__ float g_partials[NBLOCKS];
__device__ unsigned int g_done_count;  // zero-init; self-resets each call

// ---- packed f32x2 helpers (Blackwell FFMA2) ----
__device__ __forceinline__ unsigned long long ffma2(
    unsigned long long a, unsigned long long b, unsigned long long c) {
    unsigned long long d;
    asm("fma.rn.f32x2 %0, %1, %2, %3;" : "=l"(d) : "l"(a), "l"(b), "l"(c));
    return d;
}
__device__ __forceinline__ float upk_sum(unsigned long long v) {
    float lo, hi;
    asm("mov.b64 {%0, %1}, %2;" : "=f"(lo), "=f"(hi) : "l"(v));
    return lo + hi;
}

__global__ void __launch_bounds__(THREADS)
gram_loss_kernel(const float* __restrict__ views, float* __restrict__ out) {
    const int warp = threadIdx.x >> 5;
    const int lane = threadIdx.x & 31;
    const int b = blockIdx.x * WARPS_PER_BLOCK + warp;

    // Base pointers: each vector row is 512 floats = 32 x 16B per chunk-lane.
    const ulonglong2* base[KV];
#pragma unroll
    for (int k = 0; k < KV; k++)
        base[k] = reinterpret_cast<const ulonglong2*>(
            views + ((size_t)k * B + b) * (size_t)D);

    unsigned long long acc[NPAIR];
#pragma unroll
    for (int i = 0; i < NPAIR; i++) acc[i] = 0ull;

    // D=512 floats = 128 float4 per vector; 32 lanes -> 4 chunks, coalesced.
#pragma unroll
    for (int c = 0; c < 4; c++) {
        ulonglong2 v[KV];
#pragma unroll
        for (int k = 0; k < KV; k++)
            v[k] = __ldg(&base[k][c * 32 + lane]);
#pragma unroll
        for (int p = 0; p < KV; p++) {
#pragma unroll
            for (int q = p; q < KV; q++) {
                if (pair_skip(p, q)) continue;
                const int id = pidx(p, q);
                acc[id] = ffma2(v[p].x, v[q].x, acc[id]);  // d0*d0 + d1*d1 lanes
                acc[id] = ffma2(v[p].y, v[q].y, acc[id]);  // d2,d3 lanes
            }
        }
    }

    // Collapse packed lanes, then butterfly-reduce 30 partials across the warp.
    float red[NPAIR];
#pragma unroll
    for (int i = 0; i < NPAIR; i++) red[i] = upk_sum(acc[i]);
#pragma unroll
    for (int off = 16; off >= 1; off >>= 1) {
#pragma unroll
        for (int i = 0; i < NPAIR; i++)
            red[i] += __shfl_xor_sync(0xffffffffu, red[i], off);
    }

    __shared__ float warp_loss[WARPS_PER_BLOCK];
    __shared__ int sm_last;

    if (lane == 0) {
        float invn[KV];
#pragma unroll
        for (int k = 0; k < KV; k++)
            invn[k] = 1.0f / fmaxf(sqrtf(red[pidx(k, k)]), 1e-12f);

        float loss = 0.0f;
#pragma unroll
        for (int i = 0; i < S; i++) {
            const int a = i * 2;  // anchor = (s=i, v=0)
            float l[7];
            int cnt = 0;
            l[cnt++] = red[pidx(a, a + 1)] * invn[a] * invn[a + 1] * TEMP_INV;
#pragma unroll
            for (int j = 0; j < S; j++) {
                if (j == i) continue;
#pragma unroll
                for (int v2 = 0; v2 < V; v2++) {
                    const int jk = j * 2 + v2;
                    const int p = a < jk ? a : jk;
                    const int q = a < jk ? jk : a;
                    l[cnt++] = red[pidx(p, q)] * invn[a] * invn[jk] * TEMP_INV;
                }
            }
            float m = l[0];
#pragma unroll
            for (int t = 1; t < 7; t++) m = fmaxf(m, l[t]);
            float se = 0.0f;
#pragma unroll
            for (int t = 0; t < 7; t++) se += __expf(l[t] - m);
            loss += m + __logf(se) - l[0];
        }
        warp_loss[warp] = loss;
    }
    __syncthreads();

    // Block sum -> partial; last finishing block does the deterministic
    // final reduction (fixed summation order => deterministic result).
    if (threadIdx.x == 0) {
        float s = 0.0f;
#pragma unroll
        for (int w = 0; w < WARPS_PER_BLOCK; w++) s += warp_loss[w];
        g_partials[blockIdx.x] = s;
        __threadfence();
        unsigned int t = atomicAdd(&g_done_count, 1u);
        sm_last = (t == (unsigned int)(NBLOCKS - 1)) ? 1 : 0;
    }
    __syncthreads();

    if (sm_last) {
        __threadfence();  // acquire: make all g_partials stores visible
        __shared__ float sm[THREADS];
        float s = 0.0f;
        for (int i = threadIdx.x; i < NBLOCKS; i += THREADS)
            s += g_partials[i];
        sm[threadIdx.x] = s;
        __syncthreads();
#pragma unroll
        for (int stride = THREADS / 2; stride >= 1; stride >>= 1) {
            if (threadIdx.x < stride) sm[threadIdx.x] += sm[threadIdx.x + stride];
            __syncthreads();
        }
        if (threadIdx.x == 0) {
            out[0] = sm[0] / (float)(S * B);
            g_done_count = 0;  // reset for next graph replay
        }
    }
}

extern "C" void kernel_launch(void* const* d_in, const int* in_sizes, int n_in,
                              void* d_out, int out_size) {
    const float* views = (const float*)d_in[0];
    float* out = (float*)d_out;
    gram_loss_kernel<<<NBLOCKS, THREADS>>>(views, out);
}